// round 2
// baseline (speedup 1.0000x reference)
#include <cuda_runtime.h>
#include <cuda_bf16.h>

// Problem constants (reference: N_NODES=100000, FEAT=256, EMB=256, BATCH=10000, S=32)
#define BATCH_MAX 10000
#define FEAT 256
#define EMB  256
#define NSAMP 32

// Scratch (__device__ globals — no allocation allowed in kernel_launch)
__device__ float g_M[FEAT * EMB];        // Wq @ Wk^T   [F,F]
__device__ float g_bqk[FEAT];            // bq @ Wk^T   [F]
__device__ float g_u[FEAT];              // Wq @ bk     [F]
__device__ float g_d[1];                 // bq . bk
__device__ float g_qt[BATCH_MAX * FEAT]; // q-tilde     [B,F]
__device__ float g_c[BATCH_MAX];         // per-row score bias
__device__ float g_agg[BATCH_MAX * FEAT];// softmax-weighted feature agg [B,F]

// ---------------------------------------------------------------------------
// Kernel A: M[i][j] = sum_e Wq[i][e] * Wk[j][e]   (256x256x256, tiny)
// ---------------------------------------------------------------------------
__global__ void k_wqwkT(const float* __restrict__ Wq, const float* __restrict__ Wk,
                        float* __restrict__ M) {
    __shared__ float a[16][17];
    __shared__ float b[16][17];
    int tx = threadIdx.x, ty = threadIdx.y;
    int i = blockIdx.y * 16 + ty;
    int j0 = blockIdx.x * 16;
    float acc = 0.f;
    for (int e0 = 0; e0 < FEAT; e0 += 16) {
        a[ty][tx] = Wq[i * FEAT + e0 + tx];
        b[ty][tx] = Wk[(j0 + ty) * FEAT + e0 + tx];
        __syncthreads();
        #pragma unroll
        for (int k = 0; k < 16; k++) acc += a[ty][k] * b[tx][k];
        __syncthreads();
    }
    M[i * FEAT + (j0 + tx)] = acc;
}

// ---------------------------------------------------------------------------
// Small bias precompute: bqk[j] = bq . Wk[j,:] ; u[i] = Wq[i,:] . bk ; d = bq.bk
// ---------------------------------------------------------------------------
__global__ void k_bias_pre(const float* __restrict__ Wq, const float* __restrict__ bq,
                           const float* __restrict__ Wk, const float* __restrict__ bk,
                           float* __restrict__ bqk, float* __restrict__ u, float* __restrict__ d) {
    int t = threadIdx.x;  // 256 threads
    float s1 = 0.f, s2 = 0.f;
    for (int e = 0; e < FEAT; e++) {
        s1 += bq[e] * Wk[t * FEAT + e];
        s2 += Wq[t * FEAT + e] * bk[e];
    }
    bqk[t] = s1;
    u[t] = s2;
    if (t == 0) {
        float s = 0.f;
        for (int e = 0; e < FEAT; e++) s += bq[e] * bk[e];
        d[0] = s;
    }
}

// ---------------------------------------------------------------------------
// c[b] = id2feat[nodes[b]] . u + d    (one warp per row)
// ---------------------------------------------------------------------------
__global__ void k_selfdot(const float* __restrict__ id2feat, const int* __restrict__ nodes,
                          const float* __restrict__ u, const float* __restrict__ d,
                          float* __restrict__ cvec, int R) {
    int b = blockIdx.x * 8 + (threadIdx.x >> 5);
    int lane = threadIdx.x & 31;
    if (b >= R) return;
    const float* row = id2feat + (size_t)nodes[b] * FEAT;
    float s = 0.f;
    #pragma unroll
    for (int j = lane; j < FEAT; j += 32) s += row[j] * u[j];
    #pragma unroll
    for (int o = 16; o; o >>= 1) s += __shfl_down_sync(0xFFFFFFFFu, s, o);
    if (lane == 0) cvec[b] = s + d[0];
}

// ---------------------------------------------------------------------------
// SGEMM: C[r][j] = sum_k A[row(r)][k] * Bmat[k][j] + bias[j]
//   A is [*,256] (gathered by idx if GATHER), Bmat [256,256], C [R,256].
//   BM=64, BN=64, BK=16, 256 threads, 4x4 microtile.
// ---------------------------------------------------------------------------
template <bool GATHER>
__global__ void __launch_bounds__(256) k_gemm(
    const float* __restrict__ A, const int* __restrict__ idx,
    const float* __restrict__ Bmat, const float* __restrict__ bias,
    float* __restrict__ C, int R) {
    __shared__ float As[64][17];
    __shared__ float Bs[16][64];
    int tid = threadIdx.x;
    int tx = tid & 15, ty = tid >> 4;
    int r0 = blockIdx.y * 64;
    int c0 = blockIdx.x * 64;

    int arow = tid >> 2;            // 0..63
    int acol0 = (tid & 3) * 4;      // 0,4,8,12
    int gr = r0 + arow;
    bool avalid = gr < R;
    int grow = 0;
    if (avalid) grow = GATHER ? idx[gr] : gr;
    const float* Arow = A + (size_t)grow * FEAT;

    int brow = tid >> 4;            // 0..15
    int bcol0 = (tid & 15) * 4;

    float acc[4][4];
    #pragma unroll
    for (int i = 0; i < 4; i++)
        #pragma unroll
        for (int j = 0; j < 4; j++) acc[i][j] = 0.f;

    for (int kt = 0; kt < FEAT; kt += 16) {
        float4 av = avalid ? *(const float4*)(Arow + kt + acol0)
                           : make_float4(0.f, 0.f, 0.f, 0.f);
        As[arow][acol0 + 0] = av.x;
        As[arow][acol0 + 1] = av.y;
        As[arow][acol0 + 2] = av.z;
        As[arow][acol0 + 3] = av.w;
        *(float4*)&Bs[brow][bcol0] =
            *(const float4*)(Bmat + (size_t)(kt + brow) * EMB + c0 + bcol0);
        __syncthreads();
        #pragma unroll
        for (int k = 0; k < 16; k++) {
            float a[4];
            #pragma unroll
            for (int i = 0; i < 4; i++) a[i] = As[ty * 4 + i][k];
            float4 b4 = *(const float4*)&Bs[k][tx * 4];
            acc[0][0] += a[0] * b4.x; acc[0][1] += a[0] * b4.y;
            acc[0][2] += a[0] * b4.z; acc[0][3] += a[0] * b4.w;
            acc[1][0] += a[1] * b4.x; acc[1][1] += a[1] * b4.y;
            acc[1][2] += a[1] * b4.z; acc[1][3] += a[1] * b4.w;
            acc[2][0] += a[2] * b4.x; acc[2][1] += a[2] * b4.y;
            acc[2][2] += a[2] * b4.z; acc[2][3] += a[2] * b4.w;
            acc[3][0] += a[3] * b4.x; acc[3][1] += a[3] * b4.y;
            acc[3][2] += a[3] * b4.z; acc[3][3] += a[3] * b4.w;
        }
        __syncthreads();
    }

    #pragma unroll
    for (int i = 0; i < 4; i++) {
        int r = r0 + ty * 4 + i;
        if (r < R) {
            int cc = c0 + tx * 4;
            float4 o;
            o.x = acc[i][0] + bias[cc + 0];
            o.y = acc[i][1] + bias[cc + 1];
            o.z = acc[i][2] + bias[cc + 2];
            o.w = acc[i][3] + bias[cc + 3];
            *(float4*)(C + (size_t)r * EMB + cc) = o;
        }
    }
}

// ---------------------------------------------------------------------------
// Attention pass: one block per batch row.
//   scores[s] = qt[b] . feat(neigh[b,s]) + c[b]; softmax over 32;
//   agg[b] = sum_s attn[s] * feat_s
// ---------------------------------------------------------------------------
__global__ void __launch_bounds__(256) k_attn(
    const float* __restrict__ id2feat, const int* __restrict__ neigh,
    const float* __restrict__ qt, const float* __restrict__ cvec,
    float* __restrict__ agg) {
    __shared__ __align__(16) float sfeat[NSAMP][FEAT];
    __shared__ __align__(16) float sq[FEAT];
    __shared__ float sscore[NSAMP];
    __shared__ float sattn[NSAMP];

    int b = blockIdx.x;
    int tid = threadIdx.x;
    int w = tid >> 5, lane = tid & 31;

    sq[tid] = qt[(size_t)b * FEAT + tid];
    __syncthreads();

    const float4* q4 = (const float4*)sq;
    float4 q0 = q4[lane];
    float4 q1 = q4[lane + 32];

    #pragma unroll
    for (int si = 0; si < 4; si++) {
        int s = w * 4 + si;
        int idx = neigh[(size_t)b * NSAMP + s];
        const float4* row = (const float4*)(id2feat + (size_t)idx * FEAT);
        float4 v0 = row[lane];
        float4 v1 = row[lane + 32];
        ((float4*)sfeat[s])[lane] = v0;
        ((float4*)sfeat[s])[lane + 32] = v1;
        float acc = v0.x * q0.x + v0.y * q0.y + v0.z * q0.z + v0.w * q0.w +
                    v1.x * q1.x + v1.y * q1.y + v1.z * q1.z + v1.w * q1.w;
        #pragma unroll
        for (int o = 16; o; o >>= 1) acc += __shfl_down_sync(0xFFFFFFFFu, acc, o);
        if (lane == 0) sscore[s] = acc + cvec[b];
    }
    __syncthreads();

    if (w == 0) {
        float sc = sscore[lane];
        float m = sc;
        #pragma unroll
        for (int o = 16; o; o >>= 1) m = fmaxf(m, __shfl_xor_sync(0xFFFFFFFFu, m, o));
        float e = __expf(sc - m);
        float sum = e;
        #pragma unroll
        for (int o = 16; o; o >>= 1) sum += __shfl_xor_sync(0xFFFFFFFFu, sum, o);
        sattn[lane] = e / sum;
    }
    __syncthreads();

    float a = 0.f;
    #pragma unroll
    for (int s = 0; s < NSAMP; s++) a += sattn[s] * sfeat[s][tid];
    agg[(size_t)b * FEAT + tid] = a;
}

// ---------------------------------------------------------------------------
extern "C" void kernel_launch(void* const* d_in, const int* in_sizes, int n_in,
                              void* d_out, int out_size) {
    const int*   nodes   = (const int*)d_in[0];
    const int*   neigh   = (const int*)d_in[1];
    const float* id2feat = (const float*)d_in[2];
    const float* Wq      = (const float*)d_in[3];
    const float* bq      = (const float*)d_in[4];
    const float* Wk      = (const float*)d_in[5];
    const float* bk      = (const float*)d_in[6];
    const float* Wv      = (const float*)d_in[7];
    const float* bv      = (const float*)d_in[8];
    float* out = (float*)d_out;

    int B = in_sizes[0];  // 10000

    float *gM, *gbqk, *gu, *gd, *gqt, *gc, *gagg;
    cudaGetSymbolAddress((void**)&gM,   g_M);
    cudaGetSymbolAddress((void**)&gbqk, g_bqk);
    cudaGetSymbolAddress((void**)&gu,   g_u);
    cudaGetSymbolAddress((void**)&gd,   g_d);
    cudaGetSymbolAddress((void**)&gqt,  g_qt);
    cudaGetSymbolAddress((void**)&gc,   g_c);
    cudaGetSymbolAddress((void**)&gagg, g_agg);

    // 1) M = Wq @ Wk^T, bias precomputes
    k_wqwkT<<<dim3(16, 16), dim3(16, 16)>>>(Wq, Wk, gM);
    k_bias_pre<<<1, 256>>>(Wq, bq, Wk, bk, gbqk, gu, gd);

    // 2) c[b] = self . u + d
    k_selfdot<<<(B + 7) / 8, 256>>>(id2feat, nodes, gu, gd, gc, B);

    // 3) qt = gather(self) @ M + bqk
    dim3 ggrid(EMB / 64, (B + 63) / 64);
    k_gemm<true><<<ggrid, 256>>>(id2feat, nodes, gM, gbqk, gqt, B);

    // 4) scores + softmax + weighted feature aggregation
    k_attn<<<B, 256>>>(id2feat, neigh, gqt, gc, gagg);

    // 5) out = agg @ Wv + bv
    k_gemm<false><<<ggrid, 256>>>(gagg, nullptr, Wv, bv, out, B);
}

// round 3
// speedup vs baseline: 1.3273x; 1.3273x over previous
#include <cuda_runtime.h>
#include <cuda_bf16.h>

#define BATCH_MAX 10000
#define FEAT 256
#define EMB  256
#define NSAMP 32

typedef unsigned long long u64;

// Scratch
__device__ float g_M[FEAT * EMB];        // Wq @ Wk^T
__device__ float g_bqk[FEAT];            // bq @ Wk^T
__device__ float g_qt[BATCH_MAX * FEAT]; // q-tilde
__device__ float g_agg[BATCH_MAX * FEAT];// softmax-weighted feature agg

__device__ __forceinline__ u64 pk2(float x, float y) {
    u64 r;
    asm("mov.b64 %0, {%1, %2};" : "=l"(r) : "f"(x), "f"(y));
    return r;
}
__device__ __forceinline__ void upk2(float& x, float& y, u64 v) {
    asm("mov.b64 {%0, %1}, %2;" : "=f"(x), "=f"(y) : "l"(v));
}
__device__ __forceinline__ void ffma2(u64& d, u64 a, u64 b) {
    asm("fma.rn.f32x2 %0, %1, %2, %0;" : "+l"(d) : "l"(a), "l"(b));
}

// ---------------------------------------------------------------------------
// M[i][j] = sum_e Wq[i][e] * Wk[j][e]   (256x256x256, tiny)
// ---------------------------------------------------------------------------
__global__ void k_wqwkT(const float* __restrict__ Wq, const float* __restrict__ Wk,
                        float* __restrict__ M) {
    __shared__ float a[16][17];
    __shared__ float b[16][17];
    int tx = threadIdx.x, ty = threadIdx.y;
    int i = blockIdx.y * 16 + ty;
    int j0 = blockIdx.x * 16;
    float acc = 0.f;
    for (int e0 = 0; e0 < FEAT; e0 += 16) {
        a[ty][tx] = Wq[i * FEAT + e0 + tx];
        b[ty][tx] = Wk[(j0 + ty) * FEAT + e0 + tx];
        __syncthreads();
        #pragma unroll
        for (int k = 0; k < 16; k++) acc += a[ty][k] * b[tx][k];
        __syncthreads();
    }
    M[i * FEAT + (j0 + tx)] = acc;
}

// ---------------------------------------------------------------------------
// bqk[j] = bq . Wk[j,:]   (one warp per output)
// ---------------------------------------------------------------------------
__global__ void k_bqk(const float* __restrict__ Wk, const float* __restrict__ bq,
                      float* __restrict__ bqk) {
    int j = blockIdx.x * 8 + (threadIdx.x >> 5);
    int lane = threadIdx.x & 31;
    float s = 0.f;
    #pragma unroll
    for (int e = lane; e < FEAT; e += 32) s += bq[e] * Wk[j * FEAT + e];
    #pragma unroll
    for (int o = 16; o; o >>= 1) s += __shfl_down_sync(0xFFFFFFFFu, s, o);
    if (lane == 0) bqk[j] = s;
}

// ---------------------------------------------------------------------------
// SGEMM with packed f32x2 FMA: C[r][j] = sum_k A[row(r)][k]*Bmat[k][j] + bias[j]
// BM=128, BN=128, BK=8, 256 threads, 8x8 microtile (4+4 split).
// ---------------------------------------------------------------------------
template <bool GATHER>
__global__ void __launch_bounds__(256) k_gemm(
    const float* __restrict__ A, const int* __restrict__ idx,
    const float* __restrict__ Bmat, const float* __restrict__ bias,
    float* __restrict__ C, int R) {
    __shared__ float As[8][128];   // k-major
    __shared__ float Bs[8][128];
    int tid = threadIdx.x;
    int tx = tid & 15, ty = tid >> 4;
    int r0 = blockIdx.y * 128, c0 = blockIdx.x * 128;

    // A loader: row tid&127, k-cols (tid>>7)*4..+3
    int la_row = tid & 127;
    int la_col = (tid >> 7) * 4;
    int gr = r0 + la_row;
    bool av = gr < R;
    int grow = 0;
    if (av) grow = GATHER ? __ldg(idx + gr) : gr;
    const float* Arow = A + (size_t)grow * FEAT;

    // B loader: k-row tid>>5, col (tid&31)*4
    int lb_row = tid >> 5;
    int lb_col = (tid & 31) * 4;
    const float* Bld = Bmat + (size_t)lb_row * EMB + c0 + lb_col;

    u64 acc[8][4];
    #pragma unroll
    for (int i = 0; i < 8; i++)
        #pragma unroll
        for (int j = 0; j < 4; j++) acc[i][j] = 0ull;

    float4 aR = av ? *(const float4*)(Arow + la_col) : make_float4(0.f, 0.f, 0.f, 0.f);
    float4 bR = *(const float4*)Bld;

    for (int kt = 0; kt < FEAT / 8; kt++) {
        As[la_col + 0][la_row] = aR.x;
        As[la_col + 1][la_row] = aR.y;
        As[la_col + 2][la_row] = aR.z;
        As[la_col + 3][la_row] = aR.w;
        *(float4*)&Bs[lb_row][lb_col] = bR;
        __syncthreads();
        if (kt < FEAT / 8 - 1) {
            aR = av ? *(const float4*)(Arow + (kt + 1) * 8 + la_col)
                    : make_float4(0.f, 0.f, 0.f, 0.f);
            bR = *(const float4*)(Bld + (size_t)(kt + 1) * 8 * EMB);
        }
        #pragma unroll
        for (int k = 0; k < 8; k++) {
            float4 a0 = *(const float4*)&As[k][ty * 4];
            float4 a1 = *(const float4*)&As[k][64 + ty * 4];
            float4 b0 = *(const float4*)&Bs[k][tx * 4];
            float4 b1 = *(const float4*)&Bs[k][64 + tx * 4];
            u64 bp[4];
            bp[0] = pk2(b0.x, b0.y); bp[1] = pk2(b0.z, b0.w);
            bp[2] = pk2(b1.x, b1.y); bp[3] = pk2(b1.z, b1.w);
            float avals[8] = {a0.x, a0.y, a0.z, a0.w, a1.x, a1.y, a1.z, a1.w};
            #pragma unroll
            for (int i = 0; i < 8; i++) {
                u64 ap = pk2(avals[i], avals[i]);
                ffma2(acc[i][0], ap, bp[0]);
                ffma2(acc[i][1], ap, bp[1]);
                ffma2(acc[i][2], ap, bp[2]);
                ffma2(acc[i][3], ap, bp[3]);
            }
        }
        __syncthreads();
    }

    float4 bias0 = *(const float4*)(bias + c0 + tx * 4);
    float4 bias1 = *(const float4*)(bias + c0 + 64 + tx * 4);
    #pragma unroll
    for (int i = 0; i < 8; i++) {
        int r = r0 + (i < 4 ? ty * 4 + i : 64 + ty * 4 + (i - 4));
        if (r < R) {
            float4 o0, o1;
            upk2(o0.x, o0.y, acc[i][0]); upk2(o0.z, o0.w, acc[i][1]);
            upk2(o1.x, o1.y, acc[i][2]); upk2(o1.z, o1.w, acc[i][3]);
            o0.x += bias0.x; o0.y += bias0.y; o0.z += bias0.z; o0.w += bias0.w;
            o1.x += bias1.x; o1.y += bias1.y; o1.z += bias1.z; o1.w += bias1.w;
            *(float4*)(C + (size_t)r * EMB + c0 + tx * 4) = o0;
            *(float4*)(C + (size_t)r * EMB + c0 + 64 + tx * 4) = o1;
        }
    }
}

// ---------------------------------------------------------------------------
// Attention: one block per batch row. Features stay in registers.
//   scores[s] = qt[b] . feat(neigh[b,s]); softmax over 32 (shift-invariant,
//   the per-row constant c[b] is dropped); agg[b] = sum_s attn[s]*feat_s.
// ---------------------------------------------------------------------------
__global__ void __launch_bounds__(256) k_attn(
    const float* __restrict__ id2feat, const int* __restrict__ neigh,
    const float* __restrict__ qt, float* __restrict__ agg) {
    __shared__ __align__(16) float sq[FEAT];
    __shared__ float sscore[NSAMP];
    __shared__ float sattn[NSAMP];
    __shared__ __align__(16) float spart[8][FEAT];

    int b = blockIdx.x;
    int tid = threadIdx.x;
    int w = tid >> 5, lane = tid & 31;

    sq[tid] = qt[(size_t)b * FEAT + tid];
    __syncthreads();

    const float4* q4 = (const float4*)sq;
    float4 q0 = q4[lane];
    float4 q1 = q4[lane + 32];

    float4 f[4][2];
    #pragma unroll
    for (int si = 0; si < 4; si++) {
        int s = w * 4 + si;
        int idx = __ldg(neigh + (size_t)b * NSAMP + s);
        const float4* row = (const float4*)(id2feat + (size_t)idx * FEAT);
        f[si][0] = row[lane];
        f[si][1] = row[lane + 32];
        float acc = f[si][0].x * q0.x + f[si][0].y * q0.y +
                    f[si][0].z * q0.z + f[si][0].w * q0.w +
                    f[si][1].x * q1.x + f[si][1].y * q1.y +
                    f[si][1].z * q1.z + f[si][1].w * q1.w;
        #pragma unroll
        for (int o = 16; o; o >>= 1) acc += __shfl_down_sync(0xFFFFFFFFu, acc, o);
        if (lane == 0) sscore[s] = acc;
    }
    __syncthreads();

    if (w == 0) {
        float sc = sscore[lane];
        float m = sc;
        #pragma unroll
        for (int o = 16; o; o >>= 1) m = fmaxf(m, __shfl_xor_sync(0xFFFFFFFFu, m, o));
        float e = __expf(sc - m);
        float sum = e;
        #pragma unroll
        for (int o = 16; o; o >>= 1) sum += __shfl_xor_sync(0xFFFFFFFFu, sum, o);
        sattn[lane] = e / sum;
    }
    __syncthreads();

    float a0 = sattn[w * 4 + 0], a1 = sattn[w * 4 + 1];
    float a2 = sattn[w * 4 + 2], a3 = sattn[w * 4 + 3];
    float4 p0, p1;
    p0.x = f[0][0].x * a0 + f[1][0].x * a1 + f[2][0].x * a2 + f[3][0].x * a3;
    p0.y = f[0][0].y * a0 + f[1][0].y * a1 + f[2][0].y * a2 + f[3][0].y * a3;
    p0.z = f[0][0].z * a0 + f[1][0].z * a1 + f[2][0].z * a2 + f[3][0].z * a3;
    p0.w = f[0][0].w * a0 + f[1][0].w * a1 + f[2][0].w * a2 + f[3][0].w * a3;
    p1.x = f[0][1].x * a0 + f[1][1].x * a1 + f[2][1].x * a2 + f[3][1].x * a3;
    p1.y = f[0][1].y * a0 + f[1][1].y * a1 + f[2][1].y * a2 + f[3][1].y * a3;
    p1.z = f[0][1].z * a0 + f[1][1].z * a1 + f[2][1].z * a2 + f[3][1].z * a3;
    p1.w = f[0][1].w * a0 + f[1][1].w * a1 + f[2][1].w * a2 + f[3][1].w * a3;
    ((float4*)spart[w])[lane] = p0;
    ((float4*)spart[w])[lane + 32] = p1;
    __syncthreads();

    float acc = 0.f;
    #pragma unroll
    for (int ww = 0; ww < 8; ww++) acc += spart[ww][tid];
    agg[(size_t)b * FEAT + tid] = acc;
}

// ---------------------------------------------------------------------------
extern "C" void kernel_launch(void* const* d_in, const int* in_sizes, int n_in,
                              void* d_out, int out_size) {
    const int*   nodes   = (const int*)d_in[0];
    const int*   neigh   = (const int*)d_in[1];
    const float* id2feat = (const float*)d_in[2];
    const float* Wq      = (const float*)d_in[3];
    const float* bq      = (const float*)d_in[4];
    const float* Wk      = (const float*)d_in[5];
    const float* Wv      = (const float*)d_in[7];
    const float* bv      = (const float*)d_in[8];
    float* out = (float*)d_out;

    int B = in_sizes[0];  // 10000

    float *gM, *gbqk, *gqt, *gagg;
    cudaGetSymbolAddress((void**)&gM,   g_M);
    cudaGetSymbolAddress((void**)&gbqk, g_bqk);
    cudaGetSymbolAddress((void**)&gqt,  g_qt);
    cudaGetSymbolAddress((void**)&gagg, g_agg);

    // 1) M = Wq @ Wk^T ; bqk = bq @ Wk^T
    k_wqwkT<<<dim3(16, 16), dim3(16, 16)>>>(Wq, Wk, gM);
    k_bqk<<<FEAT / 8, 256>>>(Wk, bq, gbqk);

    // 2) qt = gather(self) @ M + bqk
    dim3 ggrid(EMB / 128, (B + 127) / 128);
    k_gemm<true><<<ggrid, 256>>>(id2feat, nodes, gM, gbqk, gqt, B);

    // 3) scores + softmax + weighted feature aggregation
    k_attn<<<B, 256>>>(id2feat, neigh, gqt, gagg);

    // 4) out = agg @ Wv + bv
    k_gemm<false><<<ggrid, 256>>>(gagg, nullptr, Wv, bv, out, B);
}

// round 4
// speedup vs baseline: 1.6910x; 1.2740x over previous
#include <cuda_runtime.h>
#include <cuda_bf16.h>
#include <cstdint>

#define BATCH_MAX 10000
#define FEAT 256
#define EMB  256
#define NSAMP 32

// Scratch
__device__ float g_M[FEAT * EMB];        // Wq @ Wk^T
__device__ float g_bqk[FEAT];            // bq @ Wk^T
__device__ float g_qt[BATCH_MAX * FEAT]; // q-tilde
__device__ float g_agg[BATCH_MAX * FEAT];// softmax-weighted feature agg

// ---------------------------------------------------------------------------
// TF32 helpers
// ---------------------------------------------------------------------------
__device__ __forceinline__ void tf32_split(float x, uint32_t& hi, uint32_t& lo) {
    uint32_t b;
    asm("cvt.rna.tf32.f32 %0, %1;" : "=r"(b) : "f"(x));
    float r = x - __uint_as_float(b);
    uint32_t s;
    asm("cvt.rna.tf32.f32 %0, %1;" : "=r"(s) : "f"(r));
    hi = b; lo = s;
}

__device__ __forceinline__ void mma_tf32(float* d, const uint32_t* a, const uint32_t* b) {
    asm("mma.sync.aligned.m16n8k8.row.col.f32.tf32.tf32.f32 "
        "{%0,%1,%2,%3},{%4,%5,%6,%7},{%8,%9},{%0,%1,%2,%3};"
        : "+f"(d[0]), "+f"(d[1]), "+f"(d[2]), "+f"(d[3])
        : "r"(a[0]), "r"(a[1]), "r"(a[2]), "r"(a[3]), "r"(b[0]), "r"(b[1]));
}

// ---------------------------------------------------------------------------
// M[i][j] = sum_e Wq[i][e] * Wk[j][e]   (256x256x256, tiny, fp32-exact)
// ---------------------------------------------------------------------------
__global__ void k_wqwkT(const float* __restrict__ Wq, const float* __restrict__ Wk,
                        float* __restrict__ M) {
    __shared__ float a[16][17];
    __shared__ float b[16][17];
    int tx = threadIdx.x, ty = threadIdx.y;
    int i = blockIdx.y * 16 + ty;
    int j0 = blockIdx.x * 16;
    float acc = 0.f;
    for (int e0 = 0; e0 < FEAT; e0 += 16) {
        a[ty][tx] = Wq[i * FEAT + e0 + tx];
        b[ty][tx] = Wk[(j0 + ty) * FEAT + e0 + tx];
        __syncthreads();
        #pragma unroll
        for (int k = 0; k < 16; k++) acc += a[ty][k] * b[tx][k];
        __syncthreads();
    }
    M[i * FEAT + (j0 + tx)] = acc;
}

// ---------------------------------------------------------------------------
// bqk[j] = bq . Wk[j,:]
// ---------------------------------------------------------------------------
__global__ void k_bqk(const float* __restrict__ Wk, const float* __restrict__ bq,
                      float* __restrict__ bqk) {
    int j = blockIdx.x * 8 + (threadIdx.x >> 5);
    int lane = threadIdx.x & 31;
    float s = 0.f;
    #pragma unroll
    for (int e = lane; e < FEAT; e += 32) s += bq[e] * Wk[j * FEAT + e];
    #pragma unroll
    for (int o = 16; o; o >>= 1) s += __shfl_down_sync(0xFFFFFFFFu, s, o);
    if (lane == 0) bqk[j] = s;
}

// ---------------------------------------------------------------------------
// Tensor-core GEMM (3xTF32): C[r][j] = sum_k A[row(r)][k]*B[k][j] + bias[j]
//   BM=128, BN=64, BK=32. 256 threads = 8 warps (4m x 2n), warp tile 32x32.
// ---------------------------------------------------------------------------
template <bool GATHER>
__global__ void __launch_bounds__(256) k_gemm_tc(
    const float* __restrict__ A, const int* __restrict__ idx,
    const float* __restrict__ Bmat, const float* __restrict__ bias,
    float* __restrict__ C, int R) {
    __shared__ float As[128][36];  // pad 36: frag banks = 4g+t, conflict-free
    __shared__ float Bs[32][72];   // pad 72: frag banks = 8t+g, conflict-free
    int tid = threadIdx.x;
    int wid = tid >> 5, lane = tid & 31;
    int g = lane >> 2, t = lane & 3;
    int wm = wid & 3, wn = wid >> 2;
    int r0 = blockIdx.y * 128, c0 = blockIdx.x * 64;

    // A loader: 2 threads per row, 16 floats each
    int la_row = tid >> 1;
    int la_q = (tid & 1) * 4;  // float4 index base
    int gr = r0 + la_row;
    bool av = gr < R;
    int grow = av ? (GATHER ? __ldg(idx + gr) : gr) : 0;
    const float* Arow = A + (size_t)grow * FEAT;

    // B loader: row tid>>3 (0..31), cols (tid&7)*8 .. +7
    int lb_row = tid >> 3;
    int lb_col = (tid & 7) * 8;
    const float* Bld = Bmat + (size_t)lb_row * EMB + c0 + lb_col;

    float acc[2][4][4];
    #pragma unroll
    for (int mf = 0; mf < 2; mf++)
        #pragma unroll
        for (int nf = 0; nf < 4; nf++)
            #pragma unroll
            for (int q = 0; q < 4; q++) acc[mf][nf][q] = 0.f;

    for (int kt = 0; kt < FEAT / 32; kt++) {
        #pragma unroll
        for (int q = 0; q < 4; q++) {
            float4 v = av ? *(const float4*)(Arow + kt * 32 + (la_q + q) * 4)
                          : make_float4(0.f, 0.f, 0.f, 0.f);
            *(float4*)&As[la_row][(la_q + q) * 4] = v;
        }
        #pragma unroll
        for (int q = 0; q < 2; q++) {
            float4 v = *(const float4*)(Bld + (size_t)kt * 32 * EMB + q * 4);
            *(float4*)&Bs[lb_row][lb_col + q * 4] = v;
        }
        __syncthreads();

        #pragma unroll
        for (int ks = 0; ks < 4; ks++) {
            int kb = ks * 8;
            // A fragments (2 m-frags), split into big/small tf32
            uint32_t Ab[2][4], Al[2][4];
            #pragma unroll
            for (int mf = 0; mf < 2; mf++) {
                int rb = wm * 32 + mf * 16;
                tf32_split(As[rb + g][kb + t],          Ab[mf][0], Al[mf][0]);
                tf32_split(As[rb + 8 + g][kb + t],      Ab[mf][1], Al[mf][1]);
                tf32_split(As[rb + g][kb + t + 4],      Ab[mf][2], Al[mf][2]);
                tf32_split(As[rb + 8 + g][kb + t + 4],  Ab[mf][3], Al[mf][3]);
            }
            // B fragments (4 n-frags)
            uint32_t Bb[4][2], Bl[4][2];
            #pragma unroll
            for (int nf = 0; nf < 4; nf++) {
                int nb = wn * 32 + nf * 8 + g;
                tf32_split(Bs[kb + t][nb],     Bb[nf][0], Bl[nf][0]);
                tf32_split(Bs[kb + t + 4][nb], Bb[nf][1], Bl[nf][1]);
            }
            #pragma unroll
            for (int mf = 0; mf < 2; mf++)
                #pragma unroll
                for (int nf = 0; nf < 4; nf++) {
                    mma_tf32(acc[mf][nf], Ab[mf], Bb[nf]);
                    mma_tf32(acc[mf][nf], Ab[mf], Bl[nf]);
                    mma_tf32(acc[mf][nf], Al[mf], Bb[nf]);
                }
        }
        __syncthreads();
    }

    #pragma unroll
    for (int mf = 0; mf < 2; mf++) {
        int r_lo = r0 + wm * 32 + mf * 16 + g;
        int r_hi = r_lo + 8;
        #pragma unroll
        for (int nf = 0; nf < 4; nf++) {
            int c = c0 + wn * 32 + nf * 8 + 2 * t;
            float b0 = bias[c], b1 = bias[c + 1];
            if (r_lo < R) {
                float2 v = make_float2(acc[mf][nf][0] + b0, acc[mf][nf][1] + b1);
                *(float2*)(C + (size_t)r_lo * EMB + c) = v;
            }
            if (r_hi < R) {
                float2 v = make_float2(acc[mf][nf][2] + b0, acc[mf][nf][3] + b1);
                *(float2*)(C + (size_t)r_hi * EMB + c) = v;
            }
        }
    }
}

// ---------------------------------------------------------------------------
// Attention: one block per batch row; features stay in registers.
// ---------------------------------------------------------------------------
__global__ void __launch_bounds__(256) k_attn(
    const float* __restrict__ id2feat, const int* __restrict__ neigh,
    const float* __restrict__ qt, float* __restrict__ agg) {
    __shared__ __align__(16) float sq[FEAT];
    __shared__ float sscore[NSAMP];
    __shared__ float sattn[NSAMP];
    __shared__ __align__(16) float spart[8][FEAT];

    int b = blockIdx.x;
    int tid = threadIdx.x;
    int w = tid >> 5, lane = tid & 31;

    sq[tid] = qt[(size_t)b * FEAT + tid];
    __syncthreads();

    const float4* q4 = (const float4*)sq;
    float4 q0 = q4[lane];
    float4 q1 = q4[lane + 32];

    float4 f[4][2];
    #pragma unroll
    for (int si = 0; si < 4; si++) {
        int s = w * 4 + si;
        int idx = __ldg(neigh + (size_t)b * NSAMP + s);
        const float4* row = (const float4*)(id2feat + (size_t)idx * FEAT);
        f[si][0] = row[lane];
        f[si][1] = row[lane + 32];
        float acc = f[si][0].x * q0.x + f[si][0].y * q0.y +
                    f[si][0].z * q0.z + f[si][0].w * q0.w +
                    f[si][1].x * q1.x + f[si][1].y * q1.y +
                    f[si][1].z * q1.z + f[si][1].w * q1.w;
        #pragma unroll
        for (int o = 16; o; o >>= 1) acc += __shfl_down_sync(0xFFFFFFFFu, acc, o);
        if (lane == 0) sscore[s] = acc;
    }
    __syncthreads();

    if (w == 0) {
        float sc = sscore[lane];
        float m = sc;
        #pragma unroll
        for (int o = 16; o; o >>= 1) m = fmaxf(m, __shfl_xor_sync(0xFFFFFFFFu, m, o));
        float e = __expf(sc - m);
        float sum = e;
        #pragma unroll
        for (int o = 16; o; o >>= 1) sum += __shfl_xor_sync(0xFFFFFFFFu, sum, o);
        sattn[lane] = e / sum;
    }
    __syncthreads();

    float a0 = sattn[w * 4 + 0], a1 = sattn[w * 4 + 1];
    float a2 = sattn[w * 4 + 2], a3 = sattn[w * 4 + 3];
    float4 p0, p1;
    p0.x = f[0][0].x * a0 + f[1][0].x * a1 + f[2][0].x * a2 + f[3][0].x * a3;
    p0.y = f[0][0].y * a0 + f[1][0].y * a1 + f[2][0].y * a2 + f[3][0].y * a3;
    p0.z = f[0][0].z * a0 + f[1][0].z * a1 + f[2][0].z * a2 + f[3][0].z * a3;
    p0.w = f[0][0].w * a0 + f[1][0].w * a1 + f[2][0].w * a2 + f[3][0].w * a3;
    p1.x = f[0][1].x * a0 + f[1][1].x * a1 + f[2][1].x * a2 + f[3][1].x * a3;
    p1.y = f[0][1].y * a0 + f[1][1].y * a1 + f[2][1].y * a2 + f[3][1].y * a3;
    p1.z = f[0][1].z * a0 + f[1][1].z * a1 + f[2][1].z * a2 + f[3][1].z * a3;
    p1.w = f[0][1].w * a0 + f[1][1].w * a1 + f[2][1].w * a2 + f[3][1].w * a3;
    ((float4*)spart[w])[lane] = p0;
    ((float4*)spart[w])[lane + 32] = p1;
    __syncthreads();

    float acc = 0.f;
    #pragma unroll
    for (int ww = 0; ww < 8; ww++) acc += spart[ww][tid];
    agg[(size_t)b * FEAT + tid] = acc;
}

// ---------------------------------------------------------------------------
extern "C" void kernel_launch(void* const* d_in, const int* in_sizes, int n_in,
                              void* d_out, int out_size) {
    const int*   nodes   = (const int*)d_in[0];
    const int*   neigh   = (const int*)d_in[1];
    const float* id2feat = (const float*)d_in[2];
    const float* Wq      = (const float*)d_in[3];
    const float* bq      = (const float*)d_in[4];
    const float* Wk      = (const float*)d_in[5];
    const float* Wv      = (const float*)d_in[7];
    const float* bv      = (const float*)d_in[8];
    float* out = (float*)d_out;

    int B = in_sizes[0];  // 10000

    float *gM, *gbqk, *gqt, *gagg;
    cudaGetSymbolAddress((void**)&gM,   g_M);
    cudaGetSymbolAddress((void**)&gbqk, g_bqk);
    cudaGetSymbolAddress((void**)&gqt,  g_qt);
    cudaGetSymbolAddress((void**)&gagg, g_agg);

    // 1) M = Wq @ Wk^T ; bqk = bq @ Wk^T
    k_wqwkT<<<dim3(16, 16), dim3(16, 16)>>>(Wq, Wk, gM);
    k_bqk<<<FEAT / 8, 256>>>(Wk, bq, gbqk);

    // 2) qt = gather(self) @ M + bqk   (3xTF32 tensor cores)
    dim3 ggrid(EMB / 64, (B + 127) / 128);
    k_gemm_tc<true><<<ggrid, 256>>>(id2feat, nodes, gM, gbqk, gqt, B);

    // 3) scores + softmax + weighted feature aggregation
    k_attn<<<B, 256>>>(id2feat, neigh, gqt, gagg);

    // 4) out = agg @ Wv + bv   (3xTF32 tensor cores)
    k_gemm_tc<false><<<ggrid, 256>>>(gagg, nullptr, Wv, bv, out, B);
}